// round 15
// baseline (speedup 1.0000x reference)
#include <cuda_runtime.h>
#include <cstdint>

#define NV 32
#define NE 256
#define NH 4
#define DH 64
#define K1 128
#define K2 64
#define NT 256
#define NGRAPHS 2048

#define BST 132      // xs/bufA/bufB row stride (floats), ≡4 mod 32 -> bank-perfect
#define BST4 33
#define HNS 68       // hN row stride (floats), ≡4 mod 32
#define HNS4 17
#define AM2 33       // Amat row stride in float2

// tf32 fragment scratch: [kstep][n8tile][lane][2]
#define WF_W1S 0
#define WF_W1D 32768
#define WF_W2S 65536
#define WF_W2D 81920
__device__ float g_wf[98304];

__global__ void prep_w_kernel(const float* __restrict__ W1s, const float* __restrict__ W1d,
                              const float* __restrict__ W2s, const float* __restrict__ W2d)
{
    const int i = blockIdx.x * blockDim.x + threadIdx.x;
    if (i >= 49152) return;
    const float* W; int base, idx;
    if (i < 16384)      { W = W1s; base = WF_W1S; idx = i; }
    else if (i < 32768) { W = W1d; base = WF_W1D; idx = i - 16384; }
    else if (i < 40960) { W = W2s; base = WF_W2S; idx = i - 32768; }
    else                { W = W2d; base = WF_W2D; idx = i - 40960; }
    const int t   = idx >> 10;
    const int rem = idx & 1023;
    const int n8  = rem >> 5;
    const int l   = rem & 31;
    const int k0  = t * 8 + (l & 3);
    const int n   = n8 * 8 + (l >> 2);
    const float v0 = W[k0 * 256 + n];
    const float v1 = W[(k0 + 4) * 256 + n];
    uint32_t r0, r1;
    asm("cvt.rna.tf32.f32 %0, %1;" : "=r"(r0) : "f"(v0));
    asm("cvt.rna.tf32.f32 %0, %1;" : "=r"(r1) : "f"(v1));
    g_wf[base + idx * 2 + 0] = __uint_as_float(r0);
    g_wf[base + idx * 2 + 1] = __uint_as_float(r1);
}

struct __align__(16) Smem {
    float xs[NV * BST];      // 4224 f : x node-major (layer-1 A); reused as h2 output buffer
    float bufA[NV * BST];    // 4224 f : hs half (128 cols)
    float bufB[NV * BST];    // 4224 f : hd half
    float hN[NV * HNS];      // 2176 f : maxpooled h1 (layer-2 A operand; NOT overwritten)
    float2 Amat[NV * AM2];   // 2112 f : per-half alpha matrix (2 heads)
    float logits[NE * 2];
    float aw[256];
    float mx[NV * 2];
    float den[NV * 2];
    float nalpha[NV];
    int esrc[NE];
    int edst[NE];
    int cnt[NV];
    int startv[NV + 1];
};

__device__ __forceinline__ void fma4(float4& acc, float s, const float4 w) {
    acc.x = fmaf(s, w.x, acc.x);
    acc.y = fmaf(s, w.y, acc.y);
    acc.z = fmaf(s, w.z, acc.z);
    acc.w = fmaf(s, w.w, acc.w);
}
__device__ __forceinline__ float4 max4(const float4 a, const float4 b) {
    return make_float4(fmaxf(a.x, b.x), fmaxf(a.y, b.y), fmaxf(a.z, b.z), fmaxf(a.w, b.w));
}

// C_half[32,128] = A[32,K] @ W[:, hh*128 .. +128] + b, tf32 mma m16n8k8.
// Warp w owns 2 n8-tiles (hh*16 + w*2 + {0,1}) over full m=32; B frags loaded once.
template <int T, int ASTR>
__device__ __forceinline__ void gemm_half(const float* __restrict__ Wf, int hh,
                                          const float* __restrict__ bias,
                                          const float* __restrict__ As,
                                          float* __restrict__ outb, int tid)
{
    const int w = tid >> 5, lane = tid & 31;
    const int tg = lane & 3, gid = lane >> 2;
    const int tile0 = hh * 16 + w * 2;

    float acc[2][2][4];
#pragma unroll
    for (int i = 0; i < 2; i++) {
        const int gcol = (tile0 + i) * 8 + tg * 2;
        const float b0 = __ldg(&bias[gcol]);
        const float b1 = __ldg(&bias[gcol + 1]);
#pragma unroll
        for (int mg = 0; mg < 2; mg++) {
            acc[i][mg][0] = b0; acc[i][mg][1] = b1;
            acc[i][mg][2] = b0; acc[i][mg][3] = b1;
        }
    }

#pragma unroll
    for (int t = 0; t < T; t++) {
        uint32_t a[2][4];
#pragma unroll
        for (int mg = 0; mg < 2; mg++) {
            const int row = mg * 16 + gid;
            const float f0 = As[row * ASTR + t * 8 + tg];
            const float f1 = As[(row + 8) * ASTR + t * 8 + tg];
            const float f2 = As[row * ASTR + t * 8 + tg + 4];
            const float f3 = As[(row + 8) * ASTR + t * 8 + tg + 4];
            asm("cvt.rna.tf32.f32 %0, %1;" : "=r"(a[mg][0]) : "f"(f0));
            asm("cvt.rna.tf32.f32 %0, %1;" : "=r"(a[mg][1]) : "f"(f1));
            asm("cvt.rna.tf32.f32 %0, %1;" : "=r"(a[mg][2]) : "f"(f2));
            asm("cvt.rna.tf32.f32 %0, %1;" : "=r"(a[mg][3]) : "f"(f3));
        }
        const float2* bf = reinterpret_cast<const float2*>(Wf) + ((t * 32 + tile0) * 32 + lane);
#pragma unroll
        for (int i = 0; i < 2; i++) {
            const float2 bv = __ldg(&bf[i * 32]);
            const uint32_t b0 = __float_as_uint(bv.x);
            const uint32_t b1 = __float_as_uint(bv.y);
#pragma unroll
            for (int mg = 0; mg < 2; mg++) {
                asm volatile(
                    "mma.sync.aligned.m16n8k8.row.col.f32.tf32.tf32.f32 "
                    "{%0,%1,%2,%3}, {%4,%5,%6,%7}, {%8,%9}, {%0,%1,%2,%3};"
                    : "+f"(acc[i][mg][0]), "+f"(acc[i][mg][1]),
                      "+f"(acc[i][mg][2]), "+f"(acc[i][mg][3])
                    : "r"(a[mg][0]), "r"(a[mg][1]), "r"(a[mg][2]), "r"(a[mg][3]),
                      "r"(b0), "r"(b1));
            }
        }
    }

#pragma unroll
    for (int i = 0; i < 2; i++) {
        const int col = (w * 2 + i) * 8 + tg * 2;   // col within the 128-wide half
#pragma unroll
        for (int mg = 0; mg < 2; mg++) {
            const int r0 = mg * 16 + gid;
            *reinterpret_cast<float2*>(&outb[r0 * BST + col]) =
                make_float2(acc[i][mg][0], acc[i][mg][1]);
            *reinterpret_cast<float2*>(&outb[(r0 + 8) * BST + col]) =
                make_float2(acc[i][mg][2], acc[i][mg][3]);
        }
    }
}

__device__ __forceinline__ float dot_lrelu(const float4 a, const float4 b, const float4 w) {
    float p = 0.f, v;
    v = a.x + b.x; p = fmaf(w.x, v > 0.f ? v : 0.2f * v, p);
    v = a.y + b.y; p = fmaf(w.y, v > 0.f ? v : 0.2f * v, p);
    v = a.z + b.z; p = fmaf(w.z, v > 0.f ? v : 0.2f * v, p);
    v = a.w + b.w; p = fmaf(w.w, v > 0.f ? v : 0.2f * v, p);
    return p;
}

// Edge phase for one head-pair hh. bufA = hs half, bufB = hd half (128 cols).
// Aggregation fuses head maxpool into registers; writes hNdest (running max).
// hNdest must NOT alias this layer's GEMM A-operand.
__device__ __forceinline__ void edge_phase_half(Smem& s, int hh, int tid,
                                                float* __restrict__ hNdest)
{
    float4* bufA4 = reinterpret_cast<float4*>(s.bufA);
    float4* bufB4 = reinterpret_cast<float4*>(s.bufB);
    const float4* aw4 = reinterpret_cast<const float4*>(s.aw);
    const int wid = tid >> 5, lane = tid & 31;

    // --- logits: warp walks 4 dst segments; hd + aw register-cached ---
    {
        const float4 awr = aw4[hh * 32 + lane];   // lanes 0-15: head 2hh, 16-31: head 2hh+1
#pragma unroll
        for (int si = 0; si < 4; si++) {
            const int v = wid * 4 + si;
            const int e0 = s.startv[v], e1 = s.startv[v + 1];
            if (e0 == e1) continue;
            const float4 hd = bufB4[v * BST4 + lane];
            for (int e = e0; e < e1; e++) {
                const int ss = s.esrc[e];
                float p = dot_lrelu(bufA4[ss * BST4 + lane], hd, awr);
#pragma unroll
                for (int o = 8; o; o >>= 1) p += __shfl_xor_sync(0xffffffffu, p, o);
                if ((lane & 15) == 0) s.logits[e * 2 + (lane >> 4)] = p;
            }
        }
    }
    __syncthreads();

    // --- per (node, head') max & exp-sum; others zero Amat ---
    if (tid < NV * 2) {
        const int v = tid >> 1, hp = tid & 1;
        const int e0 = s.startv[v], e1 = s.startv[v + 1];
        float m = -1e30f;
        for (int j = e0; j < e1; j++) m = fmaxf(m, s.logits[j * 2 + hp]);
        float d = 0.f;
        for (int j = e0; j < e1; j++) d += __expf(s.logits[j * 2 + hp] - m);
        s.mx[tid]  = m;
        s.den[tid] = (d == 0.f) ? 1.f : d;
    } else {
        float4* Az = reinterpret_cast<float4*>(s.Amat);
        const float4 z = make_float4(0.f, 0.f, 0.f, 0.f);
        for (int i = tid - 64; i < NV * AM2 / 2; i += NT - 64) Az[i] = z;
    }
    __syncthreads();

    // --- per-edge alpha -> Amat[dst][src] (float2 = 2 heads) ---
    {
        const int e = tid;
        const int dd = s.edst[e], ss = s.esrc[e];
        const float2 lg  = *reinterpret_cast<const float2*>(&s.logits[e * 2]);
        const float2 mxv = *reinterpret_cast<const float2*>(&s.mx[dd * 2]);
        const float2 dnv = *reinterpret_cast<const float2*>(&s.den[dd * 2]);
        float* am = reinterpret_cast<float*>(&s.Amat[dd * AM2 + ss]);
        atomicAdd(am + 0, __expf(lg.x - mxv.x) / dnv.x);
        atomicAdd(am + 1, __expf(lg.y - mxv.y) / dnv.y);
    }
    __syncthreads();

    // --- dense agg + fused head maxpool -> hNdest (running max across halves) ---
    {
        const int v = tid >> 3, l = tid & 7;
        float4 acc[4];
#pragma unroll
        for (int q = 0; q < 4; q++) acc[q] = make_float4(0.f, 0.f, 0.f, 0.f);
        const float2* AmV = s.Amat + v * AM2;
        for (int u = 0; u < NV; u++) {
            const float2 a2 = AmV[u];
            const bool nz = (a2.x != 0.f) | (a2.y != 0.f);
            if (!__any_sync(0xffffffffu, nz)) continue;
            const float4* p = bufA4 + u * BST4;
            fma4(acc[0], a2.x, p[l]);          // head' 0, in-head float4 l
            fma4(acc[1], a2.x, p[8 + l]);      // head' 0, in-head float4 8+l
            fma4(acc[2], a2.y, p[16 + l]);     // head' 1, l
            fma4(acc[3], a2.y, p[24 + l]);     // head' 1, 8+l
        }
        float4* hN4 = reinterpret_cast<float4*>(hNdest);
        const float4 m0 = max4(acc[0], acc[2]);
        const float4 m1 = max4(acc[1], acc[3]);
        if (hh == 0) {
            hN4[v * HNS4 + l]     = m0;
            hN4[v * HNS4 + 8 + l] = m1;
        } else {
            hN4[v * HNS4 + l]     = max4(hN4[v * HNS4 + l],     m0);
            hN4[v * HNS4 + 8 + l] = max4(hN4[v * HNS4 + 8 + l], m1);
        }
    }
    __syncthreads();
}

__global__ __launch_bounds__(NT, 3)
void gat_fused_kernel(const float* __restrict__ x,
                      const int* __restrict__ src,
                      const int* __restrict__ dst,
                      const float* __restrict__ b1s, const float* __restrict__ b1d,
                      const float* __restrict__ a1,
                      const float* __restrict__ b2s, const float* __restrict__ b2d,
                      const float* __restrict__ a2,
                      const float* __restrict__ Wg, const float* __restrict__ bg,
                      float* __restrict__ out)
{
    extern __shared__ unsigned char smraw[];
    Smem& s = *reinterpret_cast<Smem*>(smraw);
    const int g = blockIdx.x, tid = threadIdx.x;

    // ---- phase 0: load x node-major, count-sort edges by dst, load a1 ----
    {
        const float4* xg4 = reinterpret_cast<const float4*>(x + (size_t)g * NV * K1);
        float4* xs4 = reinterpret_cast<float4*>(s.xs);
        for (int i = tid; i < NV * K1 / 4; i += NT) {
            const int row = i >> 5, k4 = i & 31;
            xs4[row * BST4 + k4] = __ldg(&xg4[i]);
        }
        s.aw[tid] = __ldg(&a1[tid]);
        const int rs = src[g * NE + tid] - g * NV;
        const int rd = dst[g * NE + tid] - g * NV;
        if (tid < NV) s.cnt[tid] = 0;
        __syncthreads();
        const int p = atomicAdd(&s.cnt[rd], 1);
        __syncthreads();
        if (tid == 0) {
            int acc = 0;
            for (int v = 0; v < NV; v++) { s.startv[v] = acc; acc += s.cnt[v]; }
            s.startv[NV] = acc;
        }
        __syncthreads();
        const int j = s.startv[rd] + p;
        s.esrc[j] = rs;
        s.edst[j] = rd;
    }
    __syncthreads();

    // ---- layer 1: two head-pair passes (A = xs, output -> hN) ----
#pragma unroll
    for (int hh = 0; hh < 2; hh++) {
        gemm_half<16, BST>(g_wf + WF_W1S, hh, b1s, s.xs, s.bufA, tid);
        gemm_half<16, BST>(g_wf + WF_W1D, hh, b1d, s.xs, s.bufB, tid);
        __syncthreads();
        edge_phase_half(s, hh, tid, s.hN);
    }

    // ---- layer 2 (A = hN, output -> xs which is now free); reload aw for a2 ----
    s.aw[tid] = __ldg(&a2[tid]);   // race-free: aw unread until after next barrier
    float* h2 = s.xs;              // h2 buffer, HNS stride (2176 <= 4224 floats)
#pragma unroll
    for (int hh = 0; hh < 2; hh++) {
        gemm_half<8, HNS>(g_wf + WF_W2S, hh, b2s, s.hN, s.bufA, tid);
        gemm_half<8, HNS>(g_wf + WF_W2D, hh, b2d, s.hN, s.bufB, tid);
        __syncthreads();
        edge_phase_half(s, hh, tid, h2);
    }

    // ---- global attention pooling (reads h2) ----
    if (tid < NV) {
        const float4* h24 = reinterpret_cast<const float4*>(h2);
        const float4* wg4 = reinterpret_cast<const float4*>(Wg);
        float gacc = __ldg(&bg[0]);
#pragma unroll
        for (int q = 0; q < 16; q++) {
            const float4 hv = h24[tid * HNS4 + q];
            const float4 w  = __ldg(&wg4[q]);
            gacc = fmaf(hv.x, w.x, gacc);
            gacc = fmaf(hv.y, w.y, gacc);
            gacc = fmaf(hv.z, w.z, gacc);
            gacc = fmaf(hv.w, w.w, gacc);
        }
        float m = gacc;
#pragma unroll
        for (int o = 16; o; o >>= 1) m = fmaxf(m, __shfl_xor_sync(0xffffffffu, m, o));
        const float ex = __expf(gacc - m);
        float d = ex;
#pragma unroll
        for (int o = 16; o; o >>= 1) d += __shfl_xor_sync(0xffffffffu, d, o);
        s.nalpha[tid] = ex / d;
    }
    __syncthreads();
    if (tid < DH) {
        float r = 0.f;
#pragma unroll
        for (int v = 0; v < NV; v++) r = fmaf(s.nalpha[v], h2[v * HNS + tid], r);
        out[(size_t)g * DH + tid] = r;
    }
}

extern "C" void kernel_launch(void* const* d_in, const int* in_sizes, int n_in,
                              void* d_out, int out_size)
{
    const float* x   = (const float*)d_in[0];
    const int*   src = (const int*)d_in[1];
    const int*   dst = (const int*)d_in[2];
    const float* W1s = (const float*)d_in[4];
    const float* b1s = (const float*)d_in[5];
    const float* W1d = (const float*)d_in[6];
    const float* b1d = (const float*)d_in[7];
    const float* a1  = (const float*)d_in[8];
    const float* W2s = (const float*)d_in[9];
    const float* b2s = (const float*)d_in[10];
    const float* W2d = (const float*)d_in[11];
    const float* b2d = (const float*)d_in[12];
    const float* a2  = (const float*)d_in[13];
    const float* Wg  = (const float*)d_in[14];
    const float* bg  = (const float*)d_in[15];
    float* out = (float*)d_out;

    prep_w_kernel<<<192, 256>>>(W1s, W1d, W2s, W2d);

    const int smem = (int)sizeof(Smem);
    cudaFuncSetAttribute(gat_fused_kernel,
                         cudaFuncAttributeMaxDynamicSharedMemorySize, smem);
    gat_fused_kernel<<<NGRAPHS, NT, smem>>>(x, src, dst,
                                            b1s, b1d, a1,
                                            b2s, b2d, a2,
                                            Wg, bg, out);
}

// round 16
// speedup vs baseline: 1.0113x; 1.0113x over previous
#include <cuda_runtime.h>
#include <cstdint>

#define NV 32
#define NE 256
#define NH 4
#define DH 64
#define CC 256
#define K1 128
#define K2 64
#define NT 256
#define NGRAPHS 2048

#define SR4 65       // node-major row stride of buf A/B in float4
#define SRF 260
#define XSTR 132     // xs row stride (floats), 132 mod 32 = 4 -> bank-perfect mma A loads
#define XSTR4 33
#define HNS 68       // hN row stride (floats), 68 mod 32 = 4
#define HNS4 17
#define AMS 33       // Amat row stride in float4

// tf32 fragment scratch: [kstep][n8tile][lane][2]
#define WF_W1S 0
#define WF_W1D 32768
#define WF_W2S 65536
#define WF_W2D 81920
__device__ float g_wf[98304];

__global__ void prep_w_kernel(const float* __restrict__ W1s, const float* __restrict__ W1d,
                              const float* __restrict__ W2s, const float* __restrict__ W2d)
{
    const int i = blockIdx.x * blockDim.x + threadIdx.x;
    if (i >= 49152) return;
    const float* W; int base, idx;
    if (i < 16384)      { W = W1s; base = WF_W1S; idx = i; }
    else if (i < 32768) { W = W1d; base = WF_W1D; idx = i - 16384; }
    else if (i < 40960) { W = W2s; base = WF_W2S; idx = i - 32768; }
    else                { W = W2d; base = WF_W2D; idx = i - 40960; }
    const int t   = idx >> 10;
    const int rem = idx & 1023;
    const int n8  = rem >> 5;
    const int l   = rem & 31;
    const int k0  = t * 8 + (l & 3);
    const int n   = n8 * 8 + (l >> 2);
    const float v0 = W[k0 * 256 + n];
    const float v1 = W[(k0 + 4) * 256 + n];
    uint32_t r0, r1;
    asm("cvt.rna.tf32.f32 %0, %1;" : "=r"(r0) : "f"(v0));
    asm("cvt.rna.tf32.f32 %0, %1;" : "=r"(r1) : "f"(v1));
    g_wf[base + idx * 2 + 0] = __uint_as_float(r0);
    g_wf[base + idx * 2 + 1] = __uint_as_float(r1);
}

struct __align__(16) Smem {
    float xs[NV * XSTR];    // 4224 f : x node-major [row][k]; reused as Amat (exactly 4224)
    float bufA[NV * SRF];   // hs node-major
    float bufB[NV * SRF];   // hd node-major; overwritten by aggregation
    float hN[NV * HNS];     // maxpooled h node-major (layer-2 A operand + pooling + readout)
    float logits[NE * NH];
    float aw[CC];
    float mx[NV * NH];
    float den[NV * NH];
    float nalpha[NV];
    int esrc[NE];
    int edst[NE];
    int cnt[NV];
    int startv[NV + 1];
};

__device__ __forceinline__ void fma4(float4& acc, float s, const float4 w) {
    acc.x = fmaf(s, w.x, acc.x);
    acc.y = fmaf(s, w.y, acc.y);
    acc.z = fmaf(s, w.z, acc.z);
    acc.w = fmaf(s, w.w, acc.w);
}

#define MMA_TF32(ACC, A, B0, B1)                                              \
    asm volatile(                                                             \
        "mma.sync.aligned.m16n8k8.row.col.f32.tf32.tf32.f32 "                 \
        "{%0,%1,%2,%3}, {%4,%5,%6,%7}, {%8,%9}, {%0,%1,%2,%3};"               \
        : "+f"((ACC)[0]), "+f"((ACC)[1]), "+f"((ACC)[2]), "+f"((ACC)[3])      \
        : "r"((A)[0]), "r"((A)[1]), "r"((A)[2]), "r"((A)[3]),                 \
          "r"(B0), "r"(B1))

// Dual GEMM: C_s = A @ Ws + bs and C_d = A @ Wd + bd in one pass, sharing
// the A-fragment loads and cvt.rna (the A operand is identical).
// Warp w owns n8-tiles w*4..w*4+3 over the FULL m=32; each B fragment loaded once.
template <int T, int ASTR>
__device__ __forceinline__ void gemm_mma_dual(const float* __restrict__ WfS,
                                              const float* __restrict__ WfD,
                                              const float* __restrict__ biasS,
                                              const float* __restrict__ biasD,
                                              const float* __restrict__ As,
                                              float* __restrict__ outS,
                                              float* __restrict__ outD, int tid)
{
    const int w = tid >> 5, lane = tid & 31;
    const int n8b = w * 4;
    const int tg = lane & 3, gid = lane >> 2;

    float accS[4][2][4], accD[4][2][4];
#pragma unroll
    for (int i = 0; i < 4; i++) {
        const int col = (n8b + i) * 8 + tg * 2;
        const float s0 = __ldg(&biasS[col]);
        const float s1 = __ldg(&biasS[col + 1]);
        const float d0 = __ldg(&biasD[col]);
        const float d1 = __ldg(&biasD[col + 1]);
#pragma unroll
        for (int mg = 0; mg < 2; mg++) {
            accS[i][mg][0] = s0; accS[i][mg][1] = s1;
            accS[i][mg][2] = s0; accS[i][mg][3] = s1;
            accD[i][mg][0] = d0; accD[i][mg][1] = d1;
            accD[i][mg][2] = d0; accD[i][mg][3] = d1;
        }
    }

#pragma unroll
    for (int t = 0; t < T; t++) {
        uint32_t a[2][4];
#pragma unroll
        for (int mg = 0; mg < 2; mg++) {
            const int row = mg * 16 + gid;
            const float f0 = As[row * ASTR + t * 8 + tg];
            const float f1 = As[(row + 8) * ASTR + t * 8 + tg];
            const float f2 = As[row * ASTR + t * 8 + tg + 4];
            const float f3 = As[(row + 8) * ASTR + t * 8 + tg + 4];
            asm("cvt.rna.tf32.f32 %0, %1;" : "=r"(a[mg][0]) : "f"(f0));
            asm("cvt.rna.tf32.f32 %0, %1;" : "=r"(a[mg][1]) : "f"(f1));
            asm("cvt.rna.tf32.f32 %0, %1;" : "=r"(a[mg][2]) : "f"(f2));
            asm("cvt.rna.tf32.f32 %0, %1;" : "=r"(a[mg][3]) : "f"(f3));
        }
        const int fb = (t * 32 + n8b) * 32 + lane;
        const float2* bfS = reinterpret_cast<const float2*>(WfS) + fb;
        const float2* bfD = reinterpret_cast<const float2*>(WfD) + fb;
#pragma unroll
        for (int i = 0; i < 4; i++) {
            const float2 bvS = __ldg(&bfS[i * 32]);
            const float2 bvD = __ldg(&bfD[i * 32]);
            const uint32_t s0 = __float_as_uint(bvS.x), s1 = __float_as_uint(bvS.y);
            const uint32_t d0 = __float_as_uint(bvD.x), d1 = __float_as_uint(bvD.y);
#pragma unroll
            for (int mg = 0; mg < 2; mg++) {
                MMA_TF32(accS[i][mg], a[mg], s0, s1);
                MMA_TF32(accD[i][mg], a[mg], d0, d1);
            }
        }
    }

#pragma unroll
    for (int i = 0; i < 4; i++) {
        const int col = (n8b + i) * 8 + tg * 2;
#pragma unroll
        for (int mg = 0; mg < 2; mg++) {
            const int r0 = mg * 16 + gid;
            *reinterpret_cast<float2*>(&outS[r0 * SRF + col]) =
                make_float2(accS[i][mg][0], accS[i][mg][1]);
            *reinterpret_cast<float2*>(&outS[(r0 + 8) * SRF + col]) =
                make_float2(accS[i][mg][2], accS[i][mg][3]);
            *reinterpret_cast<float2*>(&outD[r0 * SRF + col]) =
                make_float2(accD[i][mg][0], accD[i][mg][1]);
            *reinterpret_cast<float2*>(&outD[(r0 + 8) * SRF + col]) =
                make_float2(accD[i][mg][2], accD[i][mg][3]);
        }
    }
}

__device__ __forceinline__ float dot_lrelu(const float4 a, const float4 b, const float4 w) {
    float p = 0.f, v;
    v = a.x + b.x; p = fmaf(w.x, v > 0.f ? v : 0.2f * v, p);
    v = a.y + b.y; p = fmaf(w.y, v > 0.f ? v : 0.2f * v, p);
    v = a.z + b.z; p = fmaf(w.z, v > 0.f ? v : 0.2f * v, p);
    v = a.w + b.w; p = fmaf(w.w, v > 0.f ? v : 0.2f * v, p);
    return p;
}

// GATv2 edge phase (identical to the 346us baseline).
__device__ __forceinline__ void gat_edge_phase(Smem& s, const float* __restrict__ attn, int tid)
{
    s.aw[tid] = __ldg(&attn[tid]);
    __syncthreads();

    float4* bufA4 = reinterpret_cast<float4*>(s.bufA);
    float4* bufB4 = reinterpret_cast<float4*>(s.bufB);
    const float4* aw4 = reinterpret_cast<const float4*>(s.aw);
    float* Amat = s.xs;
    float4* Amat4 = reinterpret_cast<float4*>(Amat);

    const int wid = tid >> 5, lane = tid & 31;

    // --- logits by dst segment ---
    {
        const float4 awr0 = aw4[lane];
        const float4 awr1 = aw4[32 + lane];
#pragma unroll
        for (int si = 0; si < 4; si++) {
            const int v = wid * 4 + si;
            const int e0 = s.startv[v], e1 = s.startv[v + 1];
            if (e0 == e1) continue;
            const float4 hd0 = bufB4[v * SR4 + lane];
            const float4 hd1 = bufB4[v * SR4 + 32 + lane];
            for (int e = e0; e < e1; e++) {
                const int ss = s.esrc[e];
                const float4 sa0 = bufA4[ss * SR4 + lane];
                const float4 sa1 = bufA4[ss * SR4 + 32 + lane];
                float p0 = dot_lrelu(sa0, hd0, awr0);
                float p1 = dot_lrelu(sa1, hd1, awr1);
#pragma unroll
                for (int o = 8; o; o >>= 1) {
                    p0 += __shfl_xor_sync(0xffffffffu, p0, o);
                    p1 += __shfl_xor_sync(0xffffffffu, p1, o);
                }
                if ((lane & 15) == 0) {
                    const int hh = lane >> 4;
                    s.logits[e * NH + hh]     = p0;
                    s.logits[e * NH + 2 + hh] = p1;
                }
            }
        }
    }
    __syncthreads();

    // --- per (node, head) max & exp-sum; other half zeroes Amat ---
    if (tid < NV * NH) {
        const int v = tid >> 2, h = tid & 3;
        const int e0 = s.startv[v], e1 = s.startv[v + 1];
        float m = -1e30f;
        for (int j = e0; j < e1; j++) m = fmaxf(m, s.logits[j * NH + h]);
        float d = 0.f;
        for (int j = e0; j < e1; j++) d += __expf(s.logits[j * NH + h] - m);
        s.mx[tid]  = m;
        s.den[tid] = (d == 0.f) ? 1.f : d;
    } else {
        const float4 z = make_float4(0.f, 0.f, 0.f, 0.f);
        for (int i = tid - 128; i < NV * AMS; i += 128) Amat4[i] = z;
    }
    __syncthreads();

    // --- per-edge alpha -> dense Amat[dst][src] ---
    {
        const int e = tid;
        const int dd = s.edst[e], ss = s.esrc[e];
        const float4 lg  = *reinterpret_cast<const float4*>(&s.logits[e * NH]);
        const float4 mxv = *reinterpret_cast<const float4*>(&s.mx[dd * NH]);
        const float4 dnv = *reinterpret_cast<const float4*>(&s.den[dd * NH]);
        float* am = Amat + (dd * AMS + ss) * 4;
        atomicAdd(am + 0, __expf(lg.x - mxv.x) / dnv.x);
        atomicAdd(am + 1, __expf(lg.y - mxv.y) / dnv.y);
        atomicAdd(am + 2, __expf(lg.z - mxv.z) / dnv.z);
        atomicAdd(am + 3, __expf(lg.w - mxv.w) / dnv.w);
    }
    __syncthreads();

    // --- dense aggregation: bufB[v] = sum_u Amat[v][u] (per head) * hs[u] ---
    {
        const int v = tid >> 3;
        const int l = tid & 7;
        float4 acc[8];
#pragma unroll
        for (int blk = 0; blk < 8; blk++) acc[blk] = make_float4(0.f, 0.f, 0.f, 0.f);
        const float4* AmV = Amat4 + v * AMS;
        for (int u = 0; u < NV; u++) {
            const float4 a4 = AmV[u];
            const bool nz = (a4.x != 0.f) | (a4.y != 0.f) | (a4.z != 0.f) | (a4.w != 0.f);
            if (!__any_sync(0xffffffffu, nz)) continue;
            const float4* p = bufA4 + u * SR4;
#pragma unroll
            for (int blk = 0; blk < 8; blk++) {
                const int h = blk >> 1;
                const float a = (h == 0) ? a4.x : (h == 1) ? a4.y : (h == 2) ? a4.z : a4.w;
                fma4(acc[blk], a, p[blk * 8 + l]);
            }
        }
#pragma unroll
        for (int blk = 0; blk < 8; blk++) bufB4[v * SR4 + blk * 8 + l] = acc[blk];
    }
    __syncthreads();

    // --- head maxpool -> hN[v][k] only ---
    float4* hN4 = reinterpret_cast<float4*>(s.hN);
    for (int i = tid; i < NV * DH / 4; i += NT) {
        const int v = i >> 4, q = i & 15;
        float4 m = bufB4[v * SR4 + q];
#pragma unroll
        for (int h = 1; h < NH; h++) {
            const float4 t = bufB4[v * SR4 + h * 16 + q];
            m.x = fmaxf(m.x, t.x); m.y = fmaxf(m.y, t.y);
            m.z = fmaxf(m.z, t.z); m.w = fmaxf(m.w, t.w);
        }
        hN4[v * HNS4 + q] = m;
    }
    __syncthreads();
}

__global__ __launch_bounds__(NT, 2)
void gat_fused_kernel(const float* __restrict__ x,
                      const int* __restrict__ src,
                      const int* __restrict__ dst,
                      const float* __restrict__ b1s, const float* __restrict__ b1d,
                      const float* __restrict__ a1,
                      const float* __restrict__ b2s, const float* __restrict__ b2d,
                      const float* __restrict__ a2,
                      const float* __restrict__ Wg, const float* __restrict__ bg,
                      float* __restrict__ out)
{
    extern __shared__ unsigned char smraw[];
    Smem& s = *reinterpret_cast<Smem*>(smraw);
    const int g = blockIdx.x, tid = threadIdx.x;

    // ---- phase 0: load x node-major, count-sort edges by dst ----
    {
        const float4* xg4 = reinterpret_cast<const float4*>(x + (size_t)g * NV * K1);
        float4* xs4 = reinterpret_cast<float4*>(s.xs);
        for (int i = tid; i < NV * K1 / 4; i += NT) {
            const int row = i >> 5, k4 = i & 31;
            xs4[row * XSTR4 + k4] = __ldg(&xg4[i]);
        }
        const int rs = src[g * NE + tid] - g * NV;
        const int rd = dst[g * NE + tid] - g * NV;
        if (tid < NV) s.cnt[tid] = 0;
        __syncthreads();
        const int p = atomicAdd(&s.cnt[rd], 1);
        __syncthreads();
        if (tid == 0) {
            int acc = 0;
            for (int v = 0; v < NV; v++) { s.startv[v] = acc; acc += s.cnt[v]; }
            s.startv[NV] = acc;
        }
        __syncthreads();
        const int j = s.startv[rd] + p;
        s.esrc[j] = rs;
        s.edst[j] = rd;
    }
    __syncthreads();

    // ---- layer 1 (fused dual tf32 mma; A = xs) ----
    gemm_mma_dual<16, XSTR>(g_wf + WF_W1S, g_wf + WF_W1D, b1s, b1d,
                            s.xs, s.bufA, s.bufB, tid);
    __syncthreads();
    gat_edge_phase(s, a1, tid);    // destroys xs (Amat alias); writes hN

    // ---- layer 2 (A = hN) ----
    gemm_mma_dual<8, HNS>(g_wf + WF_W2S, g_wf + WF_W2D, b2s, b2d,
                          s.hN, s.bufA, s.bufB, tid);
    __syncthreads();
    gat_edge_phase(s, a2, tid);    // overwrites hN with h2

    // ---- global attention pooling ----
    if (tid < NV) {
        const float4* hN4 = reinterpret_cast<const float4*>(s.hN);
        const float4* wg4 = reinterpret_cast<const float4*>(Wg);
        float gacc = __ldg(&bg[0]);
#pragma unroll
        for (int q = 0; q < 16; q++) {
            const float4 hv = hN4[tid * HNS4 + q];
            const float4 w  = __ldg(&wg4[q]);
            gacc = fmaf(hv.x, w.x, gacc);
            gacc = fmaf(hv.y, w.y, gacc);
            gacc = fmaf(hv.z, w.z, gacc);
            gacc = fmaf(hv.w, w.w, gacc);
        }
        float m = gacc;
#pragma unroll
        for (int o = 16; o; o >>= 1) m = fmaxf(m, __shfl_xor_sync(0xffffffffu, m, o));
        const float ex = __expf(gacc - m);
        float d = ex;
#pragma unroll
        for (int o = 16; o; o >>= 1) d += __shfl_xor_sync(0xffffffffu, d, o);
        s.nalpha[tid] = ex / d;
    }
    __syncthreads();
    if (tid < DH) {
        float r = 0.f;
#pragma unroll
        for (int v = 0; v < NV; v++) r = fmaf(s.nalpha[v], s.hN[v * HNS + tid], r);
        out[(size_t)g * DH + tid] = r;
    }
}

extern "C" void kernel_launch(void* const* d_in, const int* in_sizes, int n_in,
                              void* d_out, int out_size)
{
    const float* x   = (const float*)d_in[0];
    const int*   src = (const int*)d_in[1];
    const int*   dst = (const int*)d_in[2];
    const float* W1s = (const float*)d_in[4];
    const float* b1s = (const float*)d_in[5];
    const float* W1d = (const float*)d_in[6];
    const float* b1d = (const float*)d_in[7];
    const float* a1  = (const float*)d_in[8];
    const float* W2s = (const float*)d_in[9];
    const float* b2s = (const float*)d_in[10];
    const float* W2d = (const float*)d_in[11];
    const float* b2d = (const float*)d_in[12];
    const float* a2  = (const float*)d_in[13];
    const float* Wg  = (const float*)d_in[14];
    const float* bg  = (const float*)d_in[15];
    float* out = (float*)d_out;

    prep_w_kernel<<<192, 256>>>(W1s, W1d, W2s, W2d);

    const int smem = (int)sizeof(Smem);
    cudaFuncSetAttribute(gat_fused_kernel,
                         cudaFuncAttributeMaxDynamicSharedMemorySize, smem);
    gat_fused_kernel<<<NGRAPHS, NT, smem>>>(x, src, dst,
                                            b1s, b1d, a1,
                                            b2s, b2d, a2,
                                            Wg, bg, out);
}

// round 17
// speedup vs baseline: 1.0827x; 1.0706x over previous
#include <cuda_runtime.h>
#include <cstdint>

#define NV 32
#define NE 256
#define NH 4
#define DH 64
#define CC 256
#define K1 128
#define K2 64
#define NT 256
#define NGRAPHS 2048

#define SR4 65       // node-major row stride of buf A/B in float4
#define SRF 260
#define XSTR 132     // xs row stride (floats), 132 mod 32 = 4 -> bank-perfect mma A loads
#define XSTR4 33
#define HNS 68       // hN row stride (floats), 68 mod 32 = 4
#define HNS4 17
#define AMS 33       // Amat row stride in float4

// tf32 fragment scratch: [kstep][n8tile][lane][2]
#define WF_W1S 0
#define WF_W1D 32768
#define WF_W2S 65536
#define WF_W2D 81920
__device__ float g_wf[98304];

__global__ void prep_w_kernel(const float* __restrict__ W1s, const float* __restrict__ W1d,
                              const float* __restrict__ W2s, const float* __restrict__ W2d)
{
    const int i = blockIdx.x * blockDim.x + threadIdx.x;
    if (i >= 49152) return;
    const float* W; int base, idx;
    if (i < 16384)      { W = W1s; base = WF_W1S; idx = i; }
    else if (i < 32768) { W = W1d; base = WF_W1D; idx = i - 16384; }
    else if (i < 40960) { W = W2s; base = WF_W2S; idx = i - 32768; }
    else                { W = W2d; base = WF_W2D; idx = i - 40960; }
    const int t   = idx >> 10;
    const int rem = idx & 1023;
    const int n8  = rem >> 5;
    const int l   = rem & 31;
    const int k0  = t * 8 + (l & 3);
    const int n   = n8 * 8 + (l >> 2);
    const float v0 = W[k0 * 256 + n];
    const float v1 = W[(k0 + 4) * 256 + n];
    uint32_t r0, r1;
    asm("cvt.rna.tf32.f32 %0, %1;" : "=r"(r0) : "f"(v0));
    asm("cvt.rna.tf32.f32 %0, %1;" : "=r"(r1) : "f"(v1));
    g_wf[base + idx * 2 + 0] = __uint_as_float(r0);
    g_wf[base + idx * 2 + 1] = __uint_as_float(r1);
}

struct __align__(16) Smem {
    float xs[NV * XSTR];    // 4224 f : x node-major [row][k]; reused as Amat (exactly 4224)
    float bufA[NV * SRF];   // hs node-major
    float bufB[NV * SRF];   // hd node-major
    float hN[NV * HNS];     // maxpooled h node-major (layer-2 A operand + pooling + readout)
    float logits[NE * NH];
    float aw[CC];
    float mx[NV * NH];
    float den[NV * NH];
    float nalpha[NV];
    int esrc[NE];
    int edst[NE];
    int cnt[NV];
    int startv[NV + 1];
};

__device__ __forceinline__ void fma4(float4& acc, float s, const float4 w) {
    acc.x = fmaf(s, w.x, acc.x);
    acc.y = fmaf(s, w.y, acc.y);
    acc.z = fmaf(s, w.z, acc.z);
    acc.w = fmaf(s, w.w, acc.w);
}
__device__ __forceinline__ float4 max4(const float4 a, const float4 b) {
    return make_float4(fmaxf(a.x, b.x), fmaxf(a.y, b.y), fmaxf(a.z, b.z), fmaxf(a.w, b.w));
}

// C[32,256] = A[32,K] @ W[K,256] + b via tf32 mma m16n8k8 (R13-validated).
template <int T, int ASTR>
__device__ __forceinline__ void gemm_mma(const float* __restrict__ Wf,
                                         const float* __restrict__ bias,
                                         const float* __restrict__ As,
                                         float* __restrict__ outb, int tid)
{
    const int w = tid >> 5, lane = tid & 31;
    const int n8b = w * 4;
    const int tg = lane & 3, gid = lane >> 2;

    float acc[4][2][4];
#pragma unroll
    for (int i = 0; i < 4; i++) {
        const int col = (n8b + i) * 8 + tg * 2;
        const float b0 = __ldg(&bias[col]);
        const float b1 = __ldg(&bias[col + 1]);
#pragma unroll
        for (int mg = 0; mg < 2; mg++) {
            acc[i][mg][0] = b0; acc[i][mg][1] = b1;
            acc[i][mg][2] = b0; acc[i][mg][3] = b1;
        }
    }

#pragma unroll
    for (int t = 0; t < T; t++) {
        uint32_t a[2][4];
#pragma unroll
        for (int mg = 0; mg < 2; mg++) {
            const int row = mg * 16 + gid;
            const float f0 = As[row * ASTR + t * 8 + tg];
            const float f1 = As[(row + 8) * ASTR + t * 8 + tg];
            const float f2 = As[row * ASTR + t * 8 + tg + 4];
            const float f3 = As[(row + 8) * ASTR + t * 8 + tg + 4];
            asm("cvt.rna.tf32.f32 %0, %1;" : "=r"(a[mg][0]) : "f"(f0));
            asm("cvt.rna.tf32.f32 %0, %1;" : "=r"(a[mg][1]) : "f"(f1));
            asm("cvt.rna.tf32.f32 %0, %1;" : "=r"(a[mg][2]) : "f"(f2));
            asm("cvt.rna.tf32.f32 %0, %1;" : "=r"(a[mg][3]) : "f"(f3));
        }
        const float2* bf = reinterpret_cast<const float2*>(Wf) + ((t * 32 + n8b) * 32 + lane);
#pragma unroll
        for (int i = 0; i < 4; i++) {
            const float2 bv = __ldg(&bf[i * 32]);
            const uint32_t b0 = __float_as_uint(bv.x);
            const uint32_t b1 = __float_as_uint(bv.y);
#pragma unroll
            for (int mg = 0; mg < 2; mg++) {
                asm volatile(
                    "mma.sync.aligned.m16n8k8.row.col.f32.tf32.tf32.f32 "
                    "{%0,%1,%2,%3}, {%4,%5,%6,%7}, {%8,%9}, {%0,%1,%2,%3};"
                    : "+f"(acc[i][mg][0]), "+f"(acc[i][mg][1]),
                      "+f"(acc[i][mg][2]), "+f"(acc[i][mg][3])
                    : "r"(a[mg][0]), "r"(a[mg][1]), "r"(a[mg][2]), "r"(a[mg][3]),
                      "r"(b0), "r"(b1));
            }
        }
    }

#pragma unroll
    for (int i = 0; i < 4; i++) {
        const int col = (n8b + i) * 8 + tg * 2;
#pragma unroll
        for (int mg = 0; mg < 2; mg++) {
            const int r0 = mg * 16 + gid;
            *reinterpret_cast<float2*>(&outb[r0 * SRF + col]) =
                make_float2(acc[i][mg][0], acc[i][mg][1]);
            *reinterpret_cast<float2*>(&outb[(r0 + 8) * SRF + col]) =
                make_float2(acc[i][mg][2], acc[i][mg][3]);
        }
    }
}

__device__ __forceinline__ float dot_lrelu(const float4 a, const float4 b, const float4 w) {
    float p = 0.f, v;
    v = a.x + b.x; p = fmaf(w.x, v > 0.f ? v : 0.2f * v, p);
    v = a.y + b.y; p = fmaf(w.y, v > 0.f ? v : 0.2f * v, p);
    v = a.z + b.z; p = fmaf(w.z, v > 0.f ? v : 0.2f * v, p);
    v = a.w + b.w; p = fmaf(w.w, v > 0.f ? v : 0.2f * v, p);
    return p;
}

// GATv2 edge phase (R13 structure); aggregation fuses the head maxpool into
// registers and writes hN directly (bufB store + separate maxpool pass deleted).
__device__ __forceinline__ void gat_edge_phase(Smem& s, const float* __restrict__ attn, int tid)
{
    s.aw[tid] = __ldg(&attn[tid]);
    __syncthreads();

    float4* bufA4 = reinterpret_cast<float4*>(s.bufA);
    float4* bufB4 = reinterpret_cast<float4*>(s.bufB);
    const float4* aw4 = reinterpret_cast<const float4*>(s.aw);
    float* Amat = s.xs;
    float4* Amat4 = reinterpret_cast<float4*>(Amat);

    const int wid = tid >> 5, lane = tid & 31;

    // --- logits by dst segment ---
    {
        const float4 awr0 = aw4[lane];
        const float4 awr1 = aw4[32 + lane];
#pragma unroll
        for (int si = 0; si < 4; si++) {
            const int v = wid * 4 + si;
            const int e0 = s.startv[v], e1 = s.startv[v + 1];
            if (e0 == e1) continue;
            const float4 hd0 = bufB4[v * SR4 + lane];
            const float4 hd1 = bufB4[v * SR4 + 32 + lane];
            for (int e = e0; e < e1; e++) {
                const int ss = s.esrc[e];
                const float4 sa0 = bufA4[ss * SR4 + lane];
                const float4 sa1 = bufA4[ss * SR4 + 32 + lane];
                float p0 = dot_lrelu(sa0, hd0, awr0);
                float p1 = dot_lrelu(sa1, hd1, awr1);
#pragma unroll
                for (int o = 8; o; o >>= 1) {
                    p0 += __shfl_xor_sync(0xffffffffu, p0, o);
                    p1 += __shfl_xor_sync(0xffffffffu, p1, o);
                }
                if ((lane & 15) == 0) {
                    const int hh = lane >> 4;
                    s.logits[e * NH + hh]     = p0;
                    s.logits[e * NH + 2 + hh] = p1;
                }
            }
        }
    }
    __syncthreads();

    // --- per (node, head) max & exp-sum; other half zeroes Amat ---
    if (tid < NV * NH) {
        const int v = tid >> 2, h = tid & 3;
        const int e0 = s.startv[v], e1 = s.startv[v + 1];
        float m = -1e30f;
        for (int j = e0; j < e1; j++) m = fmaxf(m, s.logits[j * NH + h]);
        float d = 0.f;
        for (int j = e0; j < e1; j++) d += __expf(s.logits[j * NH + h] - m);
        s.mx[tid]  = m;
        s.den[tid] = (d == 0.f) ? 1.f : d;
    } else {
        const float4 z = make_float4(0.f, 0.f, 0.f, 0.f);
        for (int i = tid - 128; i < NV * AMS; i += 128) Amat4[i] = z;
    }
    __syncthreads();

    // --- per-edge alpha -> dense Amat[dst][src] ---
    {
        const int e = tid;
        const int dd = s.edst[e], ss = s.esrc[e];
        const float4 lg  = *reinterpret_cast<const float4*>(&s.logits[e * NH]);
        const float4 mxv = *reinterpret_cast<const float4*>(&s.mx[dd * NH]);
        const float4 dnv = *reinterpret_cast<const float4*>(&s.den[dd * NH]);
        float* am = Amat + (dd * AMS + ss) * 4;
        atomicAdd(am + 0, __expf(lg.x - mxv.x) / dnv.x);
        atomicAdd(am + 1, __expf(lg.y - mxv.y) / dnv.y);
        atomicAdd(am + 2, __expf(lg.z - mxv.z) / dnv.z);
        atomicAdd(am + 3, __expf(lg.w - mxv.w) / dnv.w);
    }
    __syncthreads();

    // --- dense aggregation + fused head maxpool -> hN directly ---
    {
        const int v = tid >> 3;
        const int l = tid & 7;
        float4 acc[8];
#pragma unroll
        for (int blk = 0; blk < 8; blk++) acc[blk] = make_float4(0.f, 0.f, 0.f, 0.f);
        const float4* AmV = Amat4 + v * AMS;
        for (int u = 0; u < NV; u++) {
            const float4 a4 = AmV[u];
            const bool nz = (a4.x != 0.f) | (a4.y != 0.f) | (a4.z != 0.f) | (a4.w != 0.f);
            if (!__any_sync(0xffffffffu, nz)) continue;
            const float4* p = bufA4 + u * SR4;
#pragma unroll
            for (int blk = 0; blk < 8; blk++) {
                const int h = blk >> 1;
                const float a = (h == 0) ? a4.x : (h == 1) ? a4.y : (h == 2) ? a4.z : a4.w;
                fma4(acc[blk], a, p[blk * 8 + l]);
            }
        }
        // acc[blk] holds head blk>>1, in-head float4 position (blk&1)*8 + l.
        // Maxpool across heads in registers:
        const float4 m0 = max4(max4(acc[0], acc[2]), max4(acc[4], acc[6]));  // pos l
        const float4 m1 = max4(max4(acc[1], acc[3]), max4(acc[5], acc[7]));  // pos 8+l
        float4* hN4 = reinterpret_cast<float4*>(s.hN);
        hN4[v * HNS4 + l]     = m0;
        hN4[v * HNS4 + 8 + l] = m1;
    }
    __syncthreads();
}

__global__ __launch_bounds__(NT, 2)
void gat_fused_kernel(const float* __restrict__ x,
                      const int* __restrict__ src,
                      const int* __restrict__ dst,
                      const float* __restrict__ b1s, const float* __restrict__ b1d,
                      const float* __restrict__ a1,
                      const float* __restrict__ b2s, const float* __restrict__ b2d,
                      const float* __restrict__ a2,
                      const float* __restrict__ Wg, const float* __restrict__ bg,
                      float* __restrict__ out)
{
    extern __shared__ unsigned char smraw[];
    Smem& s = *reinterpret_cast<Smem*>(smraw);
    const int g = blockIdx.x, tid = threadIdx.x;

    // ---- phase 0: load x node-major, count-sort edges by dst ----
    {
        const float4* xg4 = reinterpret_cast<const float4*>(x + (size_t)g * NV * K1);
        float4* xs4 = reinterpret_cast<float4*>(s.xs);
        for (int i = tid; i < NV * K1 / 4; i += NT) {
            const int row = i >> 5, k4 = i & 31;
            xs4[row * XSTR4 + k4] = __ldg(&xg4[i]);
        }
        const int rs = src[g * NE + tid] - g * NV;
        const int rd = dst[g * NE + tid] - g * NV;
        if (tid < NV) s.cnt[tid] = 0;
        __syncthreads();
        const int p = atomicAdd(&s.cnt[rd], 1);
        __syncthreads();
        if (tid == 0) {
            int acc = 0;
            for (int v = 0; v < NV; v++) { s.startv[v] = acc; acc += s.cnt[v]; }
            s.startv[NV] = acc;
        }
        __syncthreads();
        const int j = s.startv[rd] + p;
        s.esrc[j] = rs;
        s.edst[j] = rd;
    }
    __syncthreads();

    // ---- layer 1 (tf32 mma; A = xs) ----
    gemm_mma<16, XSTR>(g_wf + WF_W1S, b1s, s.xs, s.bufA, tid);
    gemm_mma<16, XSTR>(g_wf + WF_W1D, b1d, s.xs, s.bufB, tid);
    __syncthreads();
    gat_edge_phase(s, a1, tid);    // destroys xs (Amat alias); writes hN

    // ---- layer 2 (A = hN) ----
    gemm_mma<8, HNS>(g_wf + WF_W2S, b2s, s.hN, s.bufA, tid);
    gemm_mma<8, HNS>(g_wf + WF_W2D, b2d, s.hN, s.bufB, tid);
    __syncthreads();
    gat_edge_phase(s, a2, tid);    // overwrites hN with h2

    // ---- global attention pooling ----
    if (tid < NV) {
        const float4* hN4 = reinterpret_cast<const float4*>(s.hN);
        const float4* wg4 = reinterpret_cast<const float4*>(Wg);
        float gacc = __ldg(&bg[0]);
#pragma unroll
        for (int q = 0; q < 16; q++) {
            const float4 hv = hN4[tid * HNS4 + q];
            const float4 w  = __ldg(&wg4[q]);
            gacc = fmaf(hv.x, w.x, gacc);
            gacc = fmaf(hv.y, w.y, gacc);
            gacc = fmaf(hv.z, w.z, gacc);
            gacc = fmaf(hv.w, w.w, gacc);
        }
        float m = gacc;
#pragma unroll
        for (int o = 16; o; o >>= 1) m = fmaxf(m, __shfl_xor_sync(0xffffffffu, m, o));
        const float ex = __expf(gacc - m);
        float d = ex;
#pragma unroll
        for (int o = 16; o; o >>= 1) d += __shfl_xor_sync(0xffffffffu, d, o);
        s.nalpha[tid] = ex / d;
    }
    __syncthreads();
    if (tid < DH) {
        float r = 0.f;
#pragma unroll
        for (int v = 0; v < NV; v++) r = fmaf(s.nalpha[v], s.hN[v * HNS + tid], r);
        out[(size_t)g * DH + tid] = r;
    }
}

extern "C" void kernel_launch(void* const* d_in, const int* in_sizes, int n_in,
                              void* d_out, int out_size)
{
    const float* x   = (const float*)d_in[0];
    const int*   src = (const int*)d_in[1];
    const int*   dst = (const int*)d_in[2];
    const float* W1s = (const float*)d_in[4];
    const float* b1s = (const float*)d_in[5];
    const float* W1d = (const float*)d_in[6];
    const float* b1d = (const float*)d_in[7];
    const float* a1  = (const float*)d_in[8];
    const float* W2s = (const float*)d_in[9];
    const float* b2s = (const float*)d_in[10];
    const float* W2d = (const float*)d_in[11];
    const float* b2d = (const float*)d_in[12];
    const float* a2  = (const float*)d_in[13];
    const float* Wg  = (const float*)d_in[14];
    const float* bg  = (const float*)d_in[15];
    float* out = (float*)d_out;

    prep_w_kernel<<<192, 256>>>(W1s, W1d, W2s, W2d);

    const int smem = (int)sizeof(Smem);
    cudaFuncSetAttribute(gat_fused_kernel,
                         cudaFuncAttributeMaxDynamicSharedMemorySize, smem);
    gat_fused_kernel<<<NGRAPHS, NT, smem>>>(x, src, dst,
                                            b1s, b1d, a1,
                                            b2s, b2d, a2,
                                            Wg, bg, out);
}